// round 14
// baseline (speedup 1.0000x reference)
#include <cuda_runtime.h>
#include <cuda_bf16.h>

#define TWO_PI_F     6.2831853071795864769f
#define PI_F         3.14159265358979323846f
#define INV_TWO_PI_F 0.15915494309189533577f
#define INV_4PI2_F   0.025330295910584444f   // 1/(4*pi^2)
#define INV_4PI_F    0.07957747154594767f    // 1/(4*pi)

typedef unsigned long long u64;

// ---------- packed f32x2 primitives (Blackwell) ----------
__device__ __forceinline__ u64 pk2(float lo, float hi) {
    u64 r; asm("mov.b64 %0, {%1,%2};" : "=l"(r) : "f"(lo), "f"(hi)); return r;
}
__device__ __forceinline__ u64 pk2b(float v) {
    u64 r; asm("mov.b64 %0, {%1,%1};" : "=l"(r) : "f"(v)); return r;
}
__device__ __forceinline__ void upk2(u64 v, float& lo, float& hi) {
    asm("mov.b64 {%0,%1}, %2;" : "=f"(lo), "=f"(hi) : "l"(v));
}
__device__ __forceinline__ u64 f2add(u64 a, u64 b) {
    u64 r; asm("add.rn.f32x2 %0,%1,%2;" : "=l"(r) : "l"(a), "l"(b)); return r;
}
__device__ __forceinline__ u64 f2mul(u64 a, u64 b) {
    u64 r; asm("mul.rn.f32x2 %0,%1,%2;" : "=l"(r) : "l"(a), "l"(b)); return r;
}
__device__ __forceinline__ u64 f2fma(u64 a, u64 b, u64 c) {
    u64 r; asm("fma.rn.f32x2 %0,%1,%2,%3;" : "=l"(r) : "l"(a), "l"(b), "l"(c)); return r;
}

// ---------- scalar dr (per-area id precompute only) ----------
__device__ __forceinline__ float dr_s(float x) {
    return fmaf(-__sinf(x * TWO_PI_F), INV_TWO_PI_F, x);
}
__device__ __forceinline__ float hdr_s(float x) { return dr_s(dr_s(dr_s(x))); }

// ---------- v-space dr, degree-7: v' = v * (1 + H(v^2)) ----------
__device__ __forceinline__ u64 dr_v7(u64 v) {
    const u64 H3  = pk2b(-9.2444232f);
    const u64 H2  = pk2b( 12.5421093f);
    const u64 H1  = pk2b(-6.5576576f);
    const u64 HT0 = pk2b( 1.99981925f);   // 1 + H0
    u64 e = f2mul(v, v);
    u64 p = f2fma(e, H3, H2);
    p = f2fma(p, e, H1);
    p = f2fma(p, e, HT0);
    return f2mul(p, v);
}
__device__ __forceinline__ u64 hdr_v7(u64 v) { return dr_v7(dr_v7(dr_v7(v))); }

// ---------- round 1: v in, w out:  w = 2*pi * v * (1 + H(v^2)) ----------
__device__ __forceinline__ u64 dr_v7_to_w(u64 v) {
    const u64 B3 = pk2b(-58.0845070f);    // 2*pi*H3
    const u64 B2 = pk2b( 78.8044230f);    // 2*pi*H2
    const u64 B1 = pk2b(-41.2050600f);    // 2*pi*H1
    const u64 B0 = pk2b( 12.5652349f);    // 2*pi*(1+H0)
    u64 e = f2mul(v, v);
    u64 p = f2fma(e, B3, B2);
    p = f2fma(p, e, B1);
    p = f2fma(p, e, B0);
    return f2mul(p, v);
}

// ---------- w-space dr, degree-7: w' = w * (1 + H(w^2/(4*pi^2))) ----------
// H coefficients rescaled by (4*pi^2)^-k. Pure 5-op poly; no range shift.
__device__ __forceinline__ u64 dr_w7(u64 w) {
    const u64 W3 = pk2b(-1.5024550e-4f);  // H3/(4pi^2)^3
    const u64 W2 = pk2b( 8.0473300e-3f);  // H2/(4pi^2)^2
    const u64 W1 = pk2b(-1.6610770e-1f);  // H1/(4pi^2)
    const u64 W0 = pk2b( 1.99981925f);    // 1 + H0
    u64 e = f2mul(w, w);
    u64 p = f2fma(e, W3, W2);
    p = f2fma(p, e, W1);
    p = f2fma(p, e, W0);
    return f2mul(p, w);
}

// ---------- w-space dr via MUFU (exact): w' = w + sin(w) ----------
// (phi' = phi - sin(phi), phi = w + pi, sin(phi) = -sin(w))
__device__ __forceinline__ u64 dr_wsin(u64 w) {
    float lo, hi; upk2(w, lo, hi);
    u64 s = pk2(__sinf(lo), __sinf(hi));
    return f2add(w, s);
}

// ---------- x-space dr, degree-7 (final drs) ----------
__device__ __forceinline__ u64 dr_poly7(u64 x) {
    const u64 KMH = pk2b(-0.5f);
    const u64 H3  = pk2b(-9.2444232f);
    const u64 H2  = pk2b( 12.5421093f);
    const u64 H1  = pk2b(-6.5576576f);
    const u64 H0  = pk2b( 0.99981925f);
    u64 u = f2add(x, KMH);
    u64 e = f2mul(u, u);
    u64 p = f2fma(e, H3, H2);
    p = f2fma(p, e, H1);
    p = f2fma(p, e, H0);
    return f2fma(p, u, x);
}

// product of two dr results given w values: d0*d1 = ((w0+pi)(w1+pi))/(4pi^2)
//  = KI4*w0*w1 + (1/(4pi))*(w0+w1) + 0.25
__device__ __forceinline__ u64 pair_prod(u64 w0, u64 w1) {
    const u64 KI4 = pk2b(INV_4PI2_F);
    const u64 KQ  = pk2b(INV_4PI_F);
    const u64 KC  = pk2b(0.25f);
    u64 m = f2mul(w0, w1);
    u64 s = f2add(w0, w1);
    return f2fma(s, KQ, f2fma(m, KI4, KC));
}

// 2 warps per area, 4 pixels per thread. hdr(t) chain entirely in w-space:
// round1 poly (v->w), rounds 2,3 poly (w->w), round 4 MUFU (w + sin w).
__global__ __launch_bounds__(256, 3)
void deconv_masks_kernel(const float*  __restrict__ img,
                         const float4* __restrict__ mask0,
                         const float4* __restrict__ mask1,
                         const float*  __restrict__ mid,
                         float*        __restrict__ out,
                         int n_pix_total, int n_areas)
{
    __shared__ float4 part[8];

    const int tid   = threadIdx.x;
    const int lane  = tid & 31;
    const int wid   = tid >> 5;
    const int half  = wid & 1;
    const int area  = blockIdx.x * 4 + (wid >> 1);
    if (area >= n_areas) return;

    float h = 0.0f;
    if (lane < 4) h = hdr_s(mid[(size_t)area * 4 + lane]);
    const float h0 = __shfl_sync(0xffffffffu, h, 0);
    const float h1 = __shfl_sync(0xffffffffu, h, 1);
    const float h2 = __shfl_sync(0xffffffffu, h, 2);
    const float h3 = __shfl_sync(0xffffffffu, h, 3);

    // v entry: v_t = v_ah * (2h-1)
    const u64 D1_0 = pk2b(2.0f*h0 - 1.0f);
    const u64 D1_1 = pk2b(2.0f*h1 - 1.0f);
    const u64 D1_2 = pk2b(2.0f*h2 - 1.0f);
    const u64 D1_3 = pk2b(2.0f*h3 - 1.0f);
    const u64 KMH  = pk2b(-0.5f);

    const size_t base = (size_t)area * 256 + (size_t)half * 128 + lane;

    u64 mv[4];                 // unscaled mask pair (m0,m1)
    u64 accN = 0, accD = 0;    // packed (num0,num1), (den0,den1)

    // prefetch pixel 0
    float4 v0 = mask0[base];
    float4 v1 = mask1[base];
    float  iv = img[base];

    #pragma unroll
    for (int k = 0; k < 4; k++) {
        // issue next pixel's loads early
        float4 w0p, w1p; float niv = 0.0f;
        if (k < 3) {
            const size_t np = base + (size_t)(k + 1) * 32;
            w0p = mask0[np]; w1p = mask1[np]; niv = img[np];
        }

        // hdr(a) in v-space (FMA)
        u64 vh0 = hdr_v7(f2add(pk2(v0.x, v1.x), KMH));
        u64 vh1 = hdr_v7(f2add(pk2(v0.y, v1.y), KMH));
        u64 vh2 = hdr_v7(f2add(pk2(v0.z, v1.z), KMH));
        u64 vh3 = hdr_v7(f2add(pk2(v0.w, v1.w), KMH));

        // round 1: v entry mul, poly v->w (FMA)
        u64 f0 = dr_v7_to_w(f2mul(vh0, D1_0));
        u64 f1 = dr_v7_to_w(f2mul(vh1, D1_1));
        u64 f2v = dr_v7_to_w(f2mul(vh2, D1_2));
        u64 f3 = dr_v7_to_w(f2mul(vh3, D1_3));

        // rounds 2,3: w-space polys (FMA)
        f0 = dr_w7(f0);  f1 = dr_w7(f1);
        f2v = dr_w7(f2v); f3 = dr_w7(f3);
        f0 = dr_w7(f0);  f1 = dr_w7(f1);
        f2v = dr_w7(f2v); f3 = dr_w7(f3);

        // round 4: exact MUFU dr in w-space
        f0 = dr_wsin(f0);  f1 = dr_wsin(f1);
        f2v = dr_wsin(f2v); f3 = dr_wsin(f3);

        // recombine to x-space products, final drs (FMA), unscaled m
        u64 pa = pair_prod(f0, f1);
        u64 pb = pair_prod(f2v, f3);
        u64 mm = f2mul(dr_poly7(pa), dr_poly7(pb));

        mv[k] = mm;
        accN = f2fma(mm, pk2b(iv), accN);
        accD = f2add(accD, mm);

        v0 = w0p; v1 = w1p; iv = niv;
    }

    // unpack packed accumulators, butterfly over the warp
    float4 acc;
    upk2(accN, acc.x, acc.z);   // (num0, num1)
    upk2(accD, acc.y, acc.w);   // (den0, den1)

    #pragma unroll
    for (int off = 16; off > 0; off >>= 1) {
        acc.x += __shfl_xor_sync(0xffffffffu, acc.x, off);
        acc.y += __shfl_xor_sync(0xffffffffu, acc.y, off);
        acc.z += __shfl_xor_sync(0xffffffffu, acc.z, off);
        acc.w += __shfl_xor_sync(0xffffffffu, acc.w, off);
    }

    if (lane == 0) part[wid] = acc;
    __syncthreads();
    const float4 o = part[wid ^ 1];

    const float mean0 = __fdividef(acc.x + o.x, acc.y + o.y);
    const float mean1 = __fdividef(acc.z + o.z, acc.w + o.w);
    const u64 KMEAN = pk2(mean0, mean1);

    #pragma unroll
    for (int k = 0; k < 4; k++) {
        const size_t pix = base + (size_t)k * 32;
        u64 ow = f2mul(mv[k], KMEAN);
        float o0, o1; upk2(ow, o0, o1);
        out[pix]                       = o0;
        out[pix + (size_t)n_pix_total] = o1;
    }
}

extern "C" void kernel_launch(void* const* d_in, const int* in_sizes, int n_in,
                              void* d_out, int out_size) {
    const float*  img   = (const float*) d_in[0];
    const float4* mask0 = (const float4*)d_in[1];
    const float4* mask1 = (const float4*)d_in[2];
    const float*  mid   = (const float*) d_in[3];
    float*        out   = (float*)d_out;

    const int n_pix  = in_sizes[0];
    const int areas  = n_pix / 256;
    const int blocks = (areas + 3) / 4;

    deconv_masks_kernel<<<blocks, 256>>>(img, mask0, mask1, mid, out, n_pix, areas);
}

// round 15
// speedup vs baseline: 1.0391x; 1.0391x over previous
#include <cuda_runtime.h>
#include <cuda_bf16.h>

#define TWO_PI_F     6.2831853071795864769f
#define PI_F         3.14159265358979323846f
#define INV_TWO_PI_F 0.15915494309189533577f
#define INV_4PI2_F   0.025330295910584444f   // 1/(4*pi^2)

typedef unsigned long long u64;

// ---------- packed f32x2 primitives (Blackwell) ----------
__device__ __forceinline__ u64 pk2(float lo, float hi) {
    u64 r; asm("mov.b64 %0, {%1,%2};" : "=l"(r) : "f"(lo), "f"(hi)); return r;
}
__device__ __forceinline__ u64 pk2b(float v) {
    u64 r; asm("mov.b64 %0, {%1,%1};" : "=l"(r) : "f"(v)); return r;
}
__device__ __forceinline__ void upk2(u64 v, float& lo, float& hi) {
    asm("mov.b64 {%0,%1}, %2;" : "=f"(lo), "=f"(hi) : "l"(v));
}
__device__ __forceinline__ u64 f2add(u64 a, u64 b) {
    u64 r; asm("add.rn.f32x2 %0,%1,%2;" : "=l"(r) : "l"(a), "l"(b)); return r;
}
__device__ __forceinline__ u64 f2sub(u64 a, u64 b) {
    u64 r; asm("sub.rn.f32x2 %0,%1,%2;" : "=l"(r) : "l"(a), "l"(b)); return r;
}
__device__ __forceinline__ u64 f2mul(u64 a, u64 b) {
    u64 r; asm("mul.rn.f32x2 %0,%1,%2;" : "=l"(r) : "l"(a), "l"(b)); return r;
}
__device__ __forceinline__ u64 f2fma(u64 a, u64 b, u64 c) {
    u64 r; asm("fma.rn.f32x2 %0,%1,%2,%3;" : "=l"(r) : "l"(a), "l"(b), "l"(c)); return r;
}

// ---------- scalar dr (per-area id precompute only) ----------
__device__ __forceinline__ float dr_s(float x) {
    return fmaf(-__sinf(x * TWO_PI_F), INV_TWO_PI_F, x);
}
__device__ __forceinline__ float hdr_s(float x) { return dr_s(dr_s(dr_s(x))); }

// ---------- packed dr in PHASE SPACE: phi' = phi - sin(phi) (MUFU) ----------
__device__ __forceinline__ u64 dr_phase2(u64 ph) {
    float lo, hi; upk2(ph, lo, hi);
    u64 s = pk2(__sinf(lo), __sinf(hi));
    return f2sub(ph, s);
}

// ---------- v-space dr, degree-7: v' = v * (1 + H(v^2)) ----------
__device__ __forceinline__ u64 dr_v7(u64 v) {
    const u64 H3  = pk2b(-9.2444232f);
    const u64 H2  = pk2b( 12.5421093f);
    const u64 H1  = pk2b(-6.5576576f);
    const u64 HT0 = pk2b( 1.99981925f);   // 1 + H0
    u64 e = f2mul(v, v);
    u64 p = f2fma(e, H3, H2);
    p = f2fma(p, e, H1);
    p = f2fma(p, e, HT0);
    return f2mul(p, v);
}
__device__ __forceinline__ u64 hdr_v7(u64 v) { return dr_v7(dr_v7(dr_v7(v))); }

// ---------- v-space dr with PHASE output: phi = 2*pi*dr(t), input v_t = t-0.5 ----------
__device__ __forceinline__ u64 dr_v7_phase(u64 v) {
    const u64 B3  = pk2b(-58.0845070f);   // 2*pi*H3
    const u64 B2  = pk2b( 78.8044230f);   // 2*pi*H2
    const u64 B1  = pk2b(-41.2050600f);   // 2*pi*H1
    const u64 B0  = pk2b( 12.5652349f);   // 2*pi*(1+H0)
    const u64 KPI = pk2b(PI_F);
    u64 e = f2mul(v, v);
    u64 p = f2fma(e, B3, B2);
    p = f2fma(p, e, B1);
    p = f2fma(p, e, B0);
    return f2fma(p, v, KPI);
}

// ---------- x-space dr, degree-7 (final drs) ----------
__device__ __forceinline__ u64 dr_poly7(u64 x) {
    const u64 KMH = pk2b(-0.5f);
    const u64 H3  = pk2b(-9.2444232f);
    const u64 H2  = pk2b( 12.5421093f);
    const u64 H1  = pk2b(-6.5576576f);
    const u64 H0  = pk2b( 0.99981925f);
    u64 u = f2add(x, KMH);
    u64 e = f2mul(u, u);
    u64 p = f2fma(e, H3, H2);
    p = f2fma(p, e, H1);
    p = f2fma(p, e, H0);
    return f2fma(p, u, x);
}

// R12 algorithm, register-dieted: raw mask pair staged into `out` during the
// main loop (reloaded after the reduction), no explicit prefetch rotation.
// 2 warps per area, 4 pixels per thread. Per channel: v-space hdr(a),
// entry mul, poly phase-dr, 3 MUFU phase-drs; finals: 2x deg-7 poly.
__global__ __launch_bounds__(256, 4)
void deconv_masks_kernel(const float*  __restrict__ img,
                         const float4* __restrict__ mask0,
                         const float4* __restrict__ mask1,
                         const float*  __restrict__ mid,
                         float*        __restrict__ out,
                         int n_pix_total, int n_areas)
{
    __shared__ float4 part[8];

    const int tid   = threadIdx.x;
    const int lane  = tid & 31;
    const int wid   = tid >> 5;
    const int half  = wid & 1;
    const int area  = blockIdx.x * 4 + (wid >> 1);
    if (area >= n_areas) return;

    float h = 0.0f;
    if (lane < 4) h = hdr_s(mid[(size_t)area * 4 + lane]);
    const float h0 = __shfl_sync(0xffffffffu, h, 0);
    const float h1 = __shfl_sync(0xffffffffu, h, 1);
    const float h2 = __shfl_sync(0xffffffffu, h, 2);
    const float h3 = __shfl_sync(0xffffffffu, h, 3);

    // v entry: v_t = v_ah * (2h-1)
    const u64 D1_0 = pk2b(2.0f*h0 - 1.0f);
    const u64 D1_1 = pk2b(2.0f*h1 - 1.0f);
    const u64 D1_2 = pk2b(2.0f*h2 - 1.0f);
    const u64 D1_3 = pk2b(2.0f*h3 - 1.0f);
    const u64 KI4  = pk2b(INV_4PI2_F);
    const u64 KMH  = pk2b(-0.5f);

    const size_t base = (size_t)area * 256 + (size_t)half * 128 + lane;

    u64 accN = 0, accD = 0;    // packed (num0,num1), (den0,den1)

    #pragma unroll
    for (int k = 0; k < 4; k++) {
        const size_t pix = base + (size_t)k * 32;
        const float  iv  = img[pix];
        const float4 v0  = mask0[pix];
        const float4 v1  = mask1[pix];

        // hdr(a) in v-space (FMA)
        u64 vh0 = hdr_v7(f2add(pk2(v0.x, v1.x), KMH));
        u64 vh1 = hdr_v7(f2add(pk2(v0.y, v1.y), KMH));
        u64 vh2 = hdr_v7(f2add(pk2(v0.z, v1.z), KMH));
        u64 vh3 = hdr_v7(f2add(pk2(v0.w, v1.w), KMH));

        // all channels: v entry, poly phase-dr (FMA), then 3 MUFU phase-drs
        u64 f0  = dr_v7_phase(f2mul(vh0, D1_0));
        u64 f1  = dr_v7_phase(f2mul(vh1, D1_1));
        u64 f2v = dr_v7_phase(f2mul(vh2, D1_2));
        u64 f3  = dr_v7_phase(f2mul(vh3, D1_3));

        f0 = dr_phase2(f0); f1 = dr_phase2(f1);            // round 2
        f2v = dr_phase2(f2v); f3 = dr_phase2(f3);
        f0 = dr_phase2(f0); f1 = dr_phase2(f1);            // round 3
        f2v = dr_phase2(f2v); f3 = dr_phase2(f3);
        f0 = dr_phase2(f0); f1 = dr_phase2(f1);            // round 4
        f2v = dr_phase2(f2v); f3 = dr_phase2(f3);

        // back to x-space; final drs (deg-7, FMA)
        u64 pa = f2mul(f2mul(f0, f1), KI4);
        u64 pb = f2mul(f2mul(f2v, f3), KI4);
        u64 mm = f2mul(dr_poly7(pa), dr_poly7(pb));

        accN = f2fma(mm, pk2b(iv), accN);
        accD = f2add(accD, mm);

        // stage raw mask pair into out (overwritten with scaled value below)
        float m0, m1; upk2(mm, m0, m1);
        out[pix]                       = m0;
        out[pix + (size_t)n_pix_total] = m1;
    }

    // unpack packed accumulators, butterfly over the warp
    float4 acc;
    upk2(accN, acc.x, acc.z);   // (num0, num1)
    upk2(accD, acc.y, acc.w);   // (den0, den1)

    #pragma unroll
    for (int off = 16; off > 0; off >>= 1) {
        acc.x += __shfl_xor_sync(0xffffffffu, acc.x, off);
        acc.y += __shfl_xor_sync(0xffffffffu, acc.y, off);
        acc.z += __shfl_xor_sync(0xffffffffu, acc.z, off);
        acc.w += __shfl_xor_sync(0xffffffffu, acc.w, off);
    }

    if (lane == 0) part[wid] = acc;
    __syncthreads();
    const float4 o = part[wid ^ 1];

    const float mean0 = __fdividef(acc.x + o.x, acc.y + o.y);
    const float mean1 = __fdividef(acc.z + o.z, acc.w + o.w);
    const u64 KMEAN = pk2(mean0, mean1);

    // reload staged raw m (same-thread RAW, L1/L2 hit), scale, store final
    #pragma unroll
    for (int k = 0; k < 4; k++) {
        const size_t pix = base + (size_t)k * 32;
        const float m0 = out[pix];
        const float m1 = out[pix + (size_t)n_pix_total];
        u64 ow = f2mul(pk2(m0, m1), KMEAN);
        float o0, o1; upk2(ow, o0, o1);
        out[pix]                       = o0;
        out[pix + (size_t)n_pix_total] = o1;
    }
}

extern "C" void kernel_launch(void* const* d_in, const int* in_sizes, int n_in,
                              void* d_out, int out_size) {
    const float*  img   = (const float*) d_in[0];
    const float4* mask0 = (const float4*)d_in[1];
    const float4* mask1 = (const float4*)d_in[2];
    const float*  mid   = (const float*) d_in[3];
    float*        out   = (float*)d_out;

    const int n_pix  = in_sizes[0];
    const int areas  = n_pix / 256;
    const int blocks = (areas + 3) / 4;

    deconv_masks_kernel<<<blocks, 256>>>(img, mask0, mask1, mid, out, n_pix, areas);
}

// round 16
// speedup vs baseline: 1.0720x; 1.0317x over previous
#include <cuda_runtime.h>
#include <cuda_bf16.h>

#define TWO_PI_F     6.2831853071795864769f
#define PI_F         3.14159265358979323846f
#define INV_TWO_PI_F 0.15915494309189533577f
#define INV_4PI2_F   0.025330295910584444f   // 1/(4*pi^2)

typedef unsigned long long u64;

// ---------- packed f32x2 primitives (Blackwell) ----------
__device__ __forceinline__ u64 pk2(float lo, float hi) {
    u64 r; asm("mov.b64 %0, {%1,%2};" : "=l"(r) : "f"(lo), "f"(hi)); return r;
}
__device__ __forceinline__ u64 pk2b(float v) {
    u64 r; asm("mov.b64 %0, {%1,%1};" : "=l"(r) : "f"(v)); return r;
}
__device__ __forceinline__ void upk2(u64 v, float& lo, float& hi) {
    asm("mov.b64 {%0,%1}, %2;" : "=f"(lo), "=f"(hi) : "l"(v));
}
__device__ __forceinline__ u64 f2add(u64 a, u64 b) {
    u64 r; asm("add.rn.f32x2 %0,%1,%2;" : "=l"(r) : "l"(a), "l"(b)); return r;
}
__device__ __forceinline__ u64 f2sub(u64 a, u64 b) {
    u64 r; asm("sub.rn.f32x2 %0,%1,%2;" : "=l"(r) : "l"(a), "l"(b)); return r;
}
__device__ __forceinline__ u64 f2mul(u64 a, u64 b) {
    u64 r; asm("mul.rn.f32x2 %0,%1,%2;" : "=l"(r) : "l"(a), "l"(b)); return r;
}
__device__ __forceinline__ u64 f2fma(u64 a, u64 b, u64 c) {
    u64 r; asm("fma.rn.f32x2 %0,%1,%2,%3;" : "=l"(r) : "l"(a), "l"(b), "l"(c)); return r;
}

// ---------- scalar dr (per-area id precompute only) ----------
__device__ __forceinline__ float dr_s(float x) {
    return fmaf(-__sinf(x * TWO_PI_F), INV_TWO_PI_F, x);
}
__device__ __forceinline__ float hdr_s(float x) { return dr_s(dr_s(dr_s(x))); }

// ---------- packed dr in PHASE SPACE: phi' = phi - sin(phi) (MUFU) ----------
__device__ __forceinline__ u64 dr_phase2(u64 ph) {
    float lo, hi; upk2(ph, lo, hi);
    u64 s = pk2(__sinf(lo), __sinf(hi));
    return f2sub(ph, s);
}

// ---------- v-space dr, degree-7: v' = v * (1 + H(v^2)) ----------
__device__ __forceinline__ u64 dr_v7(u64 v) {
    const u64 H3  = pk2b(-9.2444232f);
    const u64 H2  = pk2b( 12.5421093f);
    const u64 H1  = pk2b(-6.5576576f);
    const u64 HT0 = pk2b( 1.99981925f);   // 1 + H0
    u64 e = f2mul(v, v);
    u64 p = f2fma(e, H3, H2);
    p = f2fma(p, e, H1);
    p = f2fma(p, e, HT0);
    return f2mul(p, v);
}
__device__ __forceinline__ u64 hdr_v7(u64 v) { return dr_v7(dr_v7(dr_v7(v))); }

// ---------- v-space dr with PHASE output: phi = 2*pi*dr(t), input v_t = t-0.5 ----------
__device__ __forceinline__ u64 dr_v7_phase(u64 v) {
    const u64 B3  = pk2b(-58.0845070f);   // 2*pi*H3
    const u64 B2  = pk2b( 78.8044230f);   // 2*pi*H2
    const u64 B1  = pk2b(-41.2050600f);   // 2*pi*H1
    const u64 B0  = pk2b( 12.5652349f);   // 2*pi*(1+H0)
    const u64 KPI = pk2b(PI_F);
    u64 e = f2mul(v, v);
    u64 p = f2fma(e, B3, B2);
    p = f2fma(p, e, B1);
    p = f2fma(p, e, B0);
    return f2fma(p, v, KPI);
}

// ---------- fused final dr: computes dr(g / (4*pi^2)) in 6 packed ops ----------
// u = fma(g, 1/4pi^2, -0.5); result = u*(1+H(u^2)) + 0.5   (same H as dr_poly7)
__device__ __forceinline__ u64 dr_final(u64 g) {
    const u64 KI4 = pk2b(INV_4PI2_F);
    const u64 KMH = pk2b(-0.5f);
    const u64 KPH = pk2b( 0.5f);
    const u64 H3  = pk2b(-9.2444232f);
    const u64 H2  = pk2b( 12.5421093f);
    const u64 H1  = pk2b(-6.5576576f);
    const u64 HT0 = pk2b( 1.99981925f);   // 1 + H0
    u64 u = f2fma(g, KI4, KMH);
    u64 e = f2mul(u, u);
    u64 p = f2fma(e, H3, H2);
    p = f2fma(p, e, H1);
    p = f2fma(p, e, HT0);
    return f2fma(p, u, KPH);
}

// R12 structure exactly; finals fused. 2 warps per area, 4 pixels per thread.
// Per channel: v-space hdr(a), entry mul, poly phase-dr, 3 MUFU phase-drs.
__global__ __launch_bounds__(256, 3)
void deconv_masks_kernel(const float*  __restrict__ img,
                         const float4* __restrict__ mask0,
                         const float4* __restrict__ mask1,
                         const float*  __restrict__ mid,
                         float*        __restrict__ out,
                         int n_pix_total, int n_areas)
{
    __shared__ float4 part[8];

    const int tid   = threadIdx.x;
    const int lane  = tid & 31;
    const int wid   = tid >> 5;
    const int half  = wid & 1;
    const int area  = blockIdx.x * 4 + (wid >> 1);
    if (area >= n_areas) return;

    float h = 0.0f;
    if (lane < 4) h = hdr_s(mid[(size_t)area * 4 + lane]);
    const float h0 = __shfl_sync(0xffffffffu, h, 0);
    const float h1 = __shfl_sync(0xffffffffu, h, 1);
    const float h2 = __shfl_sync(0xffffffffu, h, 2);
    const float h3 = __shfl_sync(0xffffffffu, h, 3);

    // v entry: v_t = v_ah * (2h-1)
    const u64 D1_0 = pk2b(2.0f*h0 - 1.0f);
    const u64 D1_1 = pk2b(2.0f*h1 - 1.0f);
    const u64 D1_2 = pk2b(2.0f*h2 - 1.0f);
    const u64 D1_3 = pk2b(2.0f*h3 - 1.0f);
    const u64 KMH  = pk2b(-0.5f);

    const size_t base = (size_t)area * 256 + (size_t)half * 128 + lane;

    u64 mv[4];                 // unscaled mask pair (m0,m1)
    u64 accN = 0, accD = 0;    // packed (num0,num1), (den0,den1)

    // prefetch pixel 0
    float4 v0 = mask0[base];
    float4 v1 = mask1[base];
    float  iv = img[base];

    #pragma unroll
    for (int k = 0; k < 4; k++) {
        // issue next pixel's loads early
        float4 w0, w1; float niv = 0.0f;
        if (k < 3) {
            const size_t np = base + (size_t)(k + 1) * 32;
            w0 = mask0[np]; w1 = mask1[np]; niv = img[np];
        }

        // hdr(a) in v-space (FMA)
        u64 vh0 = hdr_v7(f2add(pk2(v0.x, v1.x), KMH));
        u64 vh1 = hdr_v7(f2add(pk2(v0.y, v1.y), KMH));
        u64 vh2 = hdr_v7(f2add(pk2(v0.z, v1.z), KMH));
        u64 vh3 = hdr_v7(f2add(pk2(v0.w, v1.w), KMH));

        // all channels: v entry, poly phase-dr (FMA), then 3 MUFU phase-drs
        u64 f0  = dr_v7_phase(f2mul(vh0, D1_0));
        u64 f1  = dr_v7_phase(f2mul(vh1, D1_1));
        u64 f2v = dr_v7_phase(f2mul(vh2, D1_2));
        u64 f3  = dr_v7_phase(f2mul(vh3, D1_3));

        f0 = dr_phase2(f0); f1 = dr_phase2(f1);            // round 2
        f2v = dr_phase2(f2v); f3 = dr_phase2(f3);
        f0 = dr_phase2(f0); f1 = dr_phase2(f1);            // round 3
        f2v = dr_phase2(f2v); f3 = dr_phase2(f3);
        f0 = dr_phase2(f0); f1 = dr_phase2(f1);            // round 4
        f2v = dr_phase2(f2v); f3 = dr_phase2(f3);

        // fused finals: dr((f0*f1)/4pi^2) * dr((f2*f3)/4pi^2)
        u64 mm = f2mul(dr_final(f2mul(f0, f1)),
                       dr_final(f2mul(f2v, f3)));

        mv[k] = mm;
        accN = f2fma(mm, pk2b(iv), accN);
        accD = f2add(accD, mm);

        v0 = w0; v1 = w1; iv = niv;
    }

    // unpack packed accumulators, butterfly over the warp
    float4 acc;
    upk2(accN, acc.x, acc.z);   // (num0, num1)
    upk2(accD, acc.y, acc.w);   // (den0, den1)

    #pragma unroll
    for (int off = 16; off > 0; off >>= 1) {
        acc.x += __shfl_xor_sync(0xffffffffu, acc.x, off);
        acc.y += __shfl_xor_sync(0xffffffffu, acc.y, off);
        acc.z += __shfl_xor_sync(0xffffffffu, acc.z, off);
        acc.w += __shfl_xor_sync(0xffffffffu, acc.w, off);
    }

    if (lane == 0) part[wid] = acc;
    __syncthreads();
    const float4 o = part[wid ^ 1];

    const float mean0 = __fdividef(acc.x + o.x, acc.y + o.y);
    const float mean1 = __fdividef(acc.z + o.z, acc.w + o.w);
    const u64 KMEAN = pk2(mean0, mean1);

    #pragma unroll
    for (int k = 0; k < 4; k++) {
        const size_t pix = base + (size_t)k * 32;
        u64 ow = f2mul(mv[k], KMEAN);
        float o0, o1; upk2(ow, o0, o1);
        out[pix]                       = o0;
        out[pix + (size_t)n_pix_total] = o1;
    }
}

extern "C" void kernel_launch(void* const* d_in, const int* in_sizes, int n_in,
                              void* d_out, int out_size) {
    const float*  img   = (const float*) d_in[0];
    const float4* mask0 = (const float4*)d_in[1];
    const float4* mask1 = (const float4*)d_in[2];
    const float*  mid   = (const float*) d_in[3];
    float*        out   = (float*)d_out;

    const int n_pix  = in_sizes[0];
    const int areas  = n_pix / 256;
    const int blocks = (areas + 3) / 4;

    deconv_masks_kernel<<<blocks, 256>>>(img, mask0, mask1, mid, out, n_pix, areas);
}

// round 17
// speedup vs baseline: 1.0885x; 1.0154x over previous
#include <cuda_runtime.h>
#include <cuda_bf16.h>

#define TWO_PI_F     6.2831853071795864769f
#define PI_F         3.14159265358979323846f
#define INV_TWO_PI_F 0.15915494309189533577f
#define INV_4PI2_F   0.025330295910584444f   // 1/(4*pi^2)

typedef unsigned long long u64;

// ---------- packed f32x2 primitives (Blackwell) ----------
__device__ __forceinline__ u64 pk2(float lo, float hi) {
    u64 r; asm("mov.b64 %0, {%1,%2};" : "=l"(r) : "f"(lo), "f"(hi)); return r;
}
__device__ __forceinline__ u64 pk2b(float v) {
    u64 r; asm("mov.b64 %0, {%1,%1};" : "=l"(r) : "f"(v)); return r;
}
__device__ __forceinline__ void upk2(u64 v, float& lo, float& hi) {
    asm("mov.b64 {%0,%1}, %2;" : "=f"(lo), "=f"(hi) : "l"(v));
}
__device__ __forceinline__ u64 f2add(u64 a, u64 b) {
    u64 r; asm("add.rn.f32x2 %0,%1,%2;" : "=l"(r) : "l"(a), "l"(b)); return r;
}
__device__ __forceinline__ u64 f2sub(u64 a, u64 b) {
    u64 r; asm("sub.rn.f32x2 %0,%1,%2;" : "=l"(r) : "l"(a), "l"(b)); return r;
}
__device__ __forceinline__ u64 f2mul(u64 a, u64 b) {
    u64 r; asm("mul.rn.f32x2 %0,%1,%2;" : "=l"(r) : "l"(a), "l"(b)); return r;
}
__device__ __forceinline__ u64 f2fma(u64 a, u64 b, u64 c) {
    u64 r; asm("fma.rn.f32x2 %0,%1,%2,%3;" : "=l"(r) : "l"(a), "l"(b), "l"(c)); return r;
}

// ---------- scalar dr (per-area id precompute only) ----------
__device__ __forceinline__ float dr_s(float x) {
    return fmaf(-__sinf(x * TWO_PI_F), INV_TWO_PI_F, x);
}
__device__ __forceinline__ float hdr_s(float x) { return dr_s(dr_s(dr_s(x))); }

// ---------- packed dr in PHASE SPACE: phi' = phi - sin(phi) (MUFU) ----------
__device__ __forceinline__ u64 dr_phase2(u64 ph) {
    float lo, hi; upk2(ph, lo, hi);
    u64 s = pk2(__sinf(lo), __sinf(hi));
    return f2sub(ph, s);
}

// ---------- v-space dr, degree-7: v' = v * (1 + H(v^2)) ----------
__device__ __forceinline__ u64 dr_v7(u64 v) {
    const u64 H3  = pk2b(-9.2444232f);
    const u64 H2  = pk2b( 12.5421093f);
    const u64 H1  = pk2b(-6.5576576f);
    const u64 HT0 = pk2b( 1.99981925f);   // 1 + H0
    u64 e = f2mul(v, v);
    u64 p = f2fma(e, H3, H2);
    p = f2fma(p, e, H1);
    p = f2fma(p, e, HT0);
    return f2mul(p, v);
}

// ---------- v-space dr, degree-5 (middle-of-chain only): 4 packed ops ----------
// Coefficients from R8's verified deg-5 set; per-dr err ~3.9e-4 (empirical).
__device__ __forceinline__ u64 dr_v5(u64 v) {
    const u64 Q2  = pk2b( 8.4940600f);
    const u64 Q1  = pk2b(-6.0508700f);
    const u64 QT0 = pk2b( 1.9838740f);    // 1 + Q0
    u64 e = f2mul(v, v);
    u64 p = f2fma(e, Q2, Q1);
    p = f2fma(p, e, QT0);
    return f2mul(p, v);
}

// hdr(a): deg-7, deg-5, deg-7 (one deg-5 substitution = +3.9e-4 rel_err)
__device__ __forceinline__ u64 hdr_v757(u64 v) { return dr_v7(dr_v5(dr_v7(v))); }

// ---------- v-space dr with PHASE output: phi = 2*pi*dr(t), input v_t = t-0.5 ----------
__device__ __forceinline__ u64 dr_v7_phase(u64 v) {
    const u64 B3  = pk2b(-58.0845070f);   // 2*pi*H3
    const u64 B2  = pk2b( 78.8044230f);   // 2*pi*H2
    const u64 B1  = pk2b(-41.2050600f);   // 2*pi*H1
    const u64 B0  = pk2b( 12.5652349f);   // 2*pi*(1+H0)
    const u64 KPI = pk2b(PI_F);
    u64 e = f2mul(v, v);
    u64 p = f2fma(e, B3, B2);
    p = f2fma(p, e, B1);
    p = f2fma(p, e, B0);
    return f2fma(p, v, KPI);
}

// ---------- fused final dr: computes dr(g / (4*pi^2)) in 6 packed ops ----------
__device__ __forceinline__ u64 dr_final(u64 g) {
    const u64 KI4 = pk2b(INV_4PI2_F);
    const u64 KMH = pk2b(-0.5f);
    const u64 KPH = pk2b( 0.5f);
    const u64 H3  = pk2b(-9.2444232f);
    const u64 H2  = pk2b( 12.5421093f);
    const u64 H1  = pk2b(-6.5576576f);
    const u64 HT0 = pk2b( 1.99981925f);   // 1 + H0
    u64 u = f2fma(g, KI4, KMH);
    u64 e = f2mul(u, u);
    u64 p = f2fma(e, H3, H2);
    p = f2fma(p, e, H1);
    p = f2fma(p, e, HT0);
    return f2fma(p, u, KPH);
}

// 2 warps per area, 4 pixels per thread.
// Per channel: v-space hdr(a) (7/5/7), entry mul, poly phase-dr, 3 MUFU phase-drs;
// finals fused (dr(g/4pi^2) in 6 ops).
__global__ __launch_bounds__(256, 3)
void deconv_masks_kernel(const float*  __restrict__ img,
                         const float4* __restrict__ mask0,
                         const float4* __restrict__ mask1,
                         const float*  __restrict__ mid,
                         float*        __restrict__ out,
                         int n_pix_total, int n_areas)
{
    __shared__ float4 part[8];

    const int tid   = threadIdx.x;
    const int lane  = tid & 31;
    const int wid   = tid >> 5;
    const int half  = wid & 1;
    const int area  = blockIdx.x * 4 + (wid >> 1);
    if (area >= n_areas) return;

    float h = 0.0f;
    if (lane < 4) h = hdr_s(mid[(size_t)area * 4 + lane]);
    const float h0 = __shfl_sync(0xffffffffu, h, 0);
    const float h1 = __shfl_sync(0xffffffffu, h, 1);
    const float h2 = __shfl_sync(0xffffffffu, h, 2);
    const float h3 = __shfl_sync(0xffffffffu, h, 3);

    // v entry: v_t = v_ah * (2h-1)
    const u64 D1_0 = pk2b(2.0f*h0 - 1.0f);
    const u64 D1_1 = pk2b(2.0f*h1 - 1.0f);
    const u64 D1_2 = pk2b(2.0f*h2 - 1.0f);
    const u64 D1_3 = pk2b(2.0f*h3 - 1.0f);
    const u64 KMH  = pk2b(-0.5f);

    const size_t base = (size_t)area * 256 + (size_t)half * 128 + lane;

    u64 mv[4];                 // unscaled mask pair (m0,m1)
    u64 accN = 0, accD = 0;    // packed (num0,num1), (den0,den1)

    // prefetch pixel 0
    float4 v0 = mask0[base];
    float4 v1 = mask1[base];
    float  iv = img[base];

    #pragma unroll
    for (int k = 0; k < 4; k++) {
        // issue next pixel's loads early
        float4 w0, w1; float niv = 0.0f;
        if (k < 3) {
            const size_t np = base + (size_t)(k + 1) * 32;
            w0 = mask0[np]; w1 = mask1[np]; niv = img[np];
        }

        // hdr(a) in v-space (FMA), 7/5/7 chain
        u64 vh0 = hdr_v757(f2add(pk2(v0.x, v1.x), KMH));
        u64 vh1 = hdr_v757(f2add(pk2(v0.y, v1.y), KMH));
        u64 vh2 = hdr_v757(f2add(pk2(v0.z, v1.z), KMH));
        u64 vh3 = hdr_v757(f2add(pk2(v0.w, v1.w), KMH));

        // all channels: v entry, poly phase-dr (FMA), then 3 MUFU phase-drs
        u64 f0  = dr_v7_phase(f2mul(vh0, D1_0));
        u64 f1  = dr_v7_phase(f2mul(vh1, D1_1));
        u64 f2v = dr_v7_phase(f2mul(vh2, D1_2));
        u64 f3  = dr_v7_phase(f2mul(vh3, D1_3));

        f0 = dr_phase2(f0); f1 = dr_phase2(f1);            // round 2
        f2v = dr_phase2(f2v); f3 = dr_phase2(f3);
        f0 = dr_phase2(f0); f1 = dr_phase2(f1);            // round 3
        f2v = dr_phase2(f2v); f3 = dr_phase2(f3);
        f0 = dr_phase2(f0); f1 = dr_phase2(f1);            // round 4
        f2v = dr_phase2(f2v); f3 = dr_phase2(f3);

        // fused finals: dr((f0*f1)/4pi^2) * dr((f2*f3)/4pi^2)
        u64 mm = f2mul(dr_final(f2mul(f0, f1)),
                       dr_final(f2mul(f2v, f3)));

        mv[k] = mm;
        accN = f2fma(mm, pk2b(iv), accN);
        accD = f2add(accD, mm);

        v0 = w0; v1 = w1; iv = niv;
    }

    // unpack packed accumulators, butterfly over the warp
    float4 acc;
    upk2(accN, acc.x, acc.z);   // (num0, num1)
    upk2(accD, acc.y, acc.w);   // (den0, den1)

    #pragma unroll
    for (int off = 16; off > 0; off >>= 1) {
        acc.x += __shfl_xor_sync(0xffffffffu, acc.x, off);
        acc.y += __shfl_xor_sync(0xffffffffu, acc.y, off);
        acc.z += __shfl_xor_sync(0xffffffffu, acc.z, off);
        acc.w += __shfl_xor_sync(0xffffffffu, acc.w, off);
    }

    if (lane == 0) part[wid] = acc;
    __syncthreads();
    const float4 o = part[wid ^ 1];

    const float mean0 = __fdividef(acc.x + o.x, acc.y + o.y);
    const float mean1 = __fdividef(acc.z + o.z, acc.w + o.w);
    const u64 KMEAN = pk2(mean0, mean1);

    #pragma unroll
    for (int k = 0; k < 4; k++) {
        const size_t pix = base + (size_t)k * 32;
        u64 ow = f2mul(mv[k], KMEAN);
        float o0, o1; upk2(ow, o0, o1);
        out[pix]                       = o0;
        out[pix + (size_t)n_pix_total] = o1;
    }
}

extern "C" void kernel_launch(void* const* d_in, const int* in_sizes, int n_in,
                              void* d_out, int out_size) {
    const float*  img   = (const float*) d_in[0];
    const float4* mask0 = (const float4*)d_in[1];
    const float4* mask1 = (const float4*)d_in[2];
    const float*  mid   = (const float*) d_in[3];
    float*        out   = (float*)d_out;

    const int n_pix  = in_sizes[0];
    const int areas  = n_pix / 256;
    const int blocks = (areas + 3) / 4;

    deconv_masks_kernel<<<blocks, 256>>>(img, mask0, mask1, mid, out, n_pix, areas);
}